// round 4
// baseline (speedup 1.0000x reference)
#include <cuda_runtime.h>
#include <cuda_bf16.h>

#define Gg 4
#define NN 4096
#define NE 65536
#define NBES 8
#define CC 32

// ---- scratch (static __device__, no allocation) ----
__device__ int    d_cnt[Gg * NN];
__device__ int    d_rowstart[Gg * NN];
__device__ int    d_cursor[Gg * NN];
__device__ int    d_src[Gg * NE];             // src node id, CSR order
__device__ float4 d_R[Gg * NE * 2];           // Bessel basis, CSR order (premsg only)
__device__ float4 d_Y[Gg * NE * 2];           // SH values, CSR order (pass only)
__device__ float  d_g0[Gg * NE * CC];         // per-(edge,channel) scalar messages
__device__ float  d_g1[Gg * NE * CC];
__device__ float  d_g2[Gg * NE * CC];
__device__ float  d_h0[Gg * NN * CC];
__device__ float  d_h1[Gg * NN * CC];
__device__ float  d_gacc[Gg * 6];

#define PI_OVER_RC   0.5235987755982988f
#define SQRT_2_RC    0.5773502691896258f
#define SQ3F         1.7320508075688772f
#define SQRT15       3.872983346207417f
#define CY2_OVER_SQ6 1.1180339887498949f
#define CY2_OVER_SQ2 1.9364916731037085f
#define SQ2F         1.4142135623730951f
#define INV_SQ6      0.4082482904638631f
#define INV_SQ2      0.7071067811865475f
#define INV_SQ3      0.5773502691896258f

// K1: zero counters/accumulators; h0 = node_attr @ Wz
__global__ void k_init(const float* __restrict__ na, const float* __restrict__ Wz) {
    int idx = blockIdx.x * blockDim.x + threadIdx.x;
    if (idx < Gg * NN * CC) {
        int node = idx / CC;
        int c = idx & (CC - 1);
        const float* a = na + node * 3;
        d_h0[idx] = a[0] * Wz[c] + a[1] * Wz[CC + c] + a[2] * Wz[2 * CC + c];
    }
    if (idx < Gg * NN) d_cnt[idx] = 0;
    if (idx < Gg * 6) d_gacc[idx] = 0.f;
}

// K2: histogram of destinations
__global__ void k_hist(const int* __restrict__ ei) {
    int idx = blockIdx.x * blockDim.x + threadIdx.x;
    if (idx >= Gg * NE) return;
    int g = idx >> 16;
    int e = idx & (NE - 1);
    int dst = ei[g * 2 * NE + NE + e];
    atomicAdd(&d_cnt[g * NN + dst], 1);
}

// K3: exclusive scan per graph
__global__ void k_scan() {
    int g = blockIdx.x;
    int t = threadIdx.x;
    __shared__ int sm[1024];
    int base = g * NN + t * 4;
    int v0 = d_cnt[base], v1 = d_cnt[base + 1], v2 = d_cnt[base + 2], v3 = d_cnt[base + 3];
    sm[t] = v0 + v1 + v2 + v3;
    __syncthreads();
    for (int off = 1; off < 1024; off <<= 1) {
        int x = (t >= off) ? sm[t - off] : 0;
        __syncthreads();
        sm[t] += x;
        __syncthreads();
    }
    int run = (t > 0) ? sm[t - 1] : 0;
    d_rowstart[base] = run;     d_cursor[base] = run;     run += v0;
    d_rowstart[base + 1] = run; d_cursor[base + 1] = run; run += v1;
    d_rowstart[base + 2] = run; d_cursor[base + 2] = run; run += v2;
    d_rowstart[base + 3] = run; d_cursor[base + 3] = run;
}

// K4: scatter + per-edge geometry (computed ONCE, shared by both passes).
__global__ void k_scatter_geom(const int* __restrict__ ei,
                               const float* __restrict__ x,
                               const float* __restrict__ xv) {
    int idx = blockIdx.x * blockDim.x + threadIdx.x;
    if (idx >= Gg * NE) return;
    int g = idx >> 16;
    int e = idx & (NE - 1);
    int dst = ei[g * 2 * NE + NE + e];
    int src = ei[g * 2 * NE + e];
    int pos = atomicAdd(&d_cursor[g * NN + dst], 1);
    int p = g * NE + pos;
    d_src[p] = src;

    float r = x[g * NE + e];
    const float* v = xv + (g * NE + e) * 3;
    float vx = v[0], vy = v[1], vz = v[2];

    float Rr[8];
    {
        float theta = r * PI_OVER_RC;
        float s1, c1;
        __sincosf(theta, &s1, &c1);
        float tc = c1 + c1;
        float inv = (r > 1e-12f) ? (SQRT_2_RC / r) : 0.f;
        float sm1 = 0.f, sc = s1;
#pragma unroll
        for (int b = 0; b < 8; b++) {
            Rr[b] = sc * inv;
            float nx = tc * sc - sm1;
            sm1 = sc; sc = nx;
        }
        if (r <= 1e-12f) {
#pragma unroll
            for (int b = 0; b < 8; b++) Rr[b] = SQRT_2_RC * (b + 1) * PI_OVER_RC;
        }
    }

    float nv = sqrtf(vx * vx + vy * vy + vz * vz);
    float inu = 1.f / (nv + 1e-9f);
    float ux = vx * inu, uy = vy * inu, uz = vz * inu;
    float ux2 = ux * ux, uy2 = uy * uy, uz2 = uz * uz;

    d_R[p * 2 + 0] = make_float4(Rr[0], Rr[1], Rr[2], Rr[3]);
    d_R[p * 2 + 1] = make_float4(Rr[4], Rr[5], Rr[6], Rr[7]);
    d_Y[p * 2 + 0] = make_float4(SQ3F * ux, SQ3F * uy, SQ3F * uz, SQRT15 * ux * uy);
    d_Y[p * 2 + 1] = make_float4(SQRT15 * uy * uz,
                                 CY2_OVER_SQ6 * (2.f * uz2 - ux2 - uy2),
                                 SQRT15 * ux * uz,
                                 CY2_OVER_SQ2 * (ux2 - uy2));
}

// K5: edge-parallel premessage: g_l[e,c] = (R[e]·Wrad[:,c,l]) * h[src[e],c]
// one warp handles 32 consecutive CSR positions; lane = channel.
template <bool PASS1>
__global__ void __launch_bounds__(256, 4)
k_premsg(const float* __restrict__ Wrad) {
    int warp = (blockIdx.x * blockDim.x + threadIdx.x) >> 5;  // Gg*NE/32 warps
    int lane = threadIdx.x & 31;
    int base = warp << 5;            // CSR position base
    int g = base >> 16;

    float wr[NBES][3];
#pragma unroll
    for (int b = 0; b < NBES; b++) {
        wr[b][0] = Wrad[b * 96 + lane * 3 + 0];
        wr[b][1] = Wrad[b * 96 + lane * 3 + 1];
        wr[b][2] = Wrad[b * 96 + lane * 3 + 2];
    }

    const float* hbase = (PASS1 ? d_h0 : d_h1) + g * NN * CC + lane;
    int s = d_src[base + lane];      // 32 srcs via one coalesced load

#pragma unroll 4
    for (int i = 0; i < 32; i++) {
        int si = __shfl_sync(0xffffffffu, s, i);
        float4 Ra = d_R[(base + i) * 2 + 0];
        float4 Rb = d_R[(base + i) * 2 + 1];
        float hs = hbase[si * CC];
        float w0 = Ra.x * wr[0][0] + Ra.y * wr[1][0] + Ra.z * wr[2][0] + Ra.w * wr[3][0]
                 + Rb.x * wr[4][0] + Rb.y * wr[5][0] + Rb.z * wr[6][0] + Rb.w * wr[7][0];
        float w1 = Ra.x * wr[0][1] + Ra.y * wr[1][1] + Ra.z * wr[2][1] + Ra.w * wr[3][1]
                 + Rb.x * wr[4][1] + Rb.y * wr[5][1] + Rb.z * wr[6][1] + Rb.w * wr[7][1];
        float w2 = Ra.x * wr[0][2] + Ra.y * wr[1][2] + Ra.z * wr[2][2] + Ra.w * wr[3][2]
                 + Rb.x * wr[4][2] + Rb.y * wr[5][2] + Rb.z * wr[6][2] + Rb.w * wr[7][2];
        int o = (base + i) * CC + lane;
        d_g0[o] = w0 * hs;
        d_g1[o] = w1 * hs;
        d_g2[o] = w2 * hs;
    }
}

// K6: node-parallel pass: pure streaming reduction + prod3body + readout
template <bool PASS1>
__global__ void __launch_bounds__(256, 5)
k_pass(const float* __restrict__ Wp,
       const float* __restrict__ Wr0, const float* __restrict__ Wr2,
       const float* __restrict__ Wm0) {
    __shared__ float sWm0[CC * CC];
    if (PASS1) {
        for (int i = threadIdx.x; i < CC * CC; i += blockDim.x) sWm0[i] = Wm0[i];
        __syncthreads();
    }

    int warp = (blockIdx.x * blockDim.x + threadIdx.x) >> 5;   // Gg*NN warps
    int lane = threadIdx.x & 31;
    int g = warp >> 12;
    int n = warp & (NN - 1);

    int start = d_rowstart[g * NN + n];
    int deg = d_cnt[g * NN + n];
    int p = g * NE + start;

    const float*  pg0 = d_g0 + p * CC + lane;
    const float*  pg1 = d_g1 + p * CC + lane;
    const float*  pg2 = d_g2 + p * CC + lane;
    const float4* pY  = d_Y + p * 2;

    float a0 = 0.f, a1x = 0.f, a1y = 0.f, a1z = 0.f;
    float q0 = 0.f, q1 = 0.f, q2 = 0.f, q3 = 0.f, q4 = 0.f;

#pragma unroll 4
    for (int i = 0; i < deg; i++) {
        float g0v = pg0[i * CC];
        float g1v = pg1[i * CC];
        float g2v = pg2[i * CC];
        float4 Ya = pY[i * 2 + 0];
        float4 Yb = pY[i * 2 + 1];
        a0 += g0v;
        a1x += g1v * Ya.x; a1y += g1v * Ya.y; a1z += g1v * Ya.z;
        q0 += g2v * Ya.w;  q1 += g2v * Yb.x;  q2 += g2v * Yb.y;
        q3 += g2v * Yb.z;  q4 += g2v * Yb.w;
    }

    // ---- prod3body (paths 0 and 2; path 1 never consumed by readout) ----
    float d11 = a1x * a1x + a1y * a1y + a1z * a1z;
    float d22 = q0 * q0 + q1 * q1 + q2 * q2 + q3 * q3 + q4 * q4;
    float B0 = Wp[lane] * a0 * a0 + Wp[CC + lane] * d11 + Wp[2 * CC + lane] * d22;

    float t5a = SQ2F * a1x * a1y;
    float t5b = SQ2F * a1y * a1z;
    float t5c = (2.f * a1z * a1z - a1x * a1x - a1y * a1y) * INV_SQ6;
    float t5d = SQ2F * a1x * a1z;
    float t5e = (a1x * a1x - a1y * a1y) * INV_SQ2;
    float w5 = Wp[5 * CC + lane], w6 = Wp[6 * CC + lane];
    float B2a = w5 * a0 * q0 + w6 * t5a;
    float B2b = w5 * a0 * q1 + w6 * t5b;
    float B2c = w5 * a0 * q2 + w6 * t5c;
    float B2d = w5 * a0 * q3 + w6 * t5d;
    float B2e = w5 * a0 * q4 + w6 * t5e;

    // ---- readout partials ----
    float wr0 = Wr0[lane], wr2 = Wr2[lane];
    float sv = B0 * wr0;
    float t0v = B2a * wr2, t1v = B2b * wr2, t2v = B2c * wr2;
    float t3v = B2d * wr2, t4v = B2e * wr2;
#pragma unroll
    for (int off = 16; off; off >>= 1) {
        sv  += __shfl_xor_sync(0xffffffffu, sv, off);
        t0v += __shfl_xor_sync(0xffffffffu, t0v, off);
        t1v += __shfl_xor_sync(0xffffffffu, t1v, off);
        t2v += __shfl_xor_sync(0xffffffffu, t2v, off);
        t3v += __shfl_xor_sync(0xffffffffu, t3v, off);
        t4v += __shfl_xor_sync(0xffffffffu, t4v, off);
    }
    if (lane == 0) {
        atomicAdd(&d_gacc[g * 6 + 0], sv);
        atomicAdd(&d_gacc[g * 6 + 1], t0v);
        atomicAdd(&d_gacc[g * 6 + 2], t1v);
        atomicAdd(&d_gacc[g * 6 + 3], t2v);
        atomicAdd(&d_gacc[g * 6 + 4], t3v);
        atomicAdd(&d_gacc[g * 6 + 5], t4v);
    }

    // ---- node scalar update (pass1 only): f0 = silu(B0 @ Wm0) ----
    if (PASS1) {
        float f = 0.f;
#pragma unroll
        for (int k = 0; k < 32; k++) {
            float bk = __shfl_sync(0xffffffffu, B0, k);
            f += bk * sWm0[k * CC + lane];
        }
        f = f / (1.f + __expf(-f));
        d_h1[(g * NN + n) * CC + lane] = f;
    }
}

// K7: finalize -> out[g] = s/sqrt3 * I + mat_from_t5(t)
__global__ void k_finalize(float* __restrict__ out) {
    int g = threadIdx.x;
    if (g >= Gg) return;
    float s = d_gacc[g * 6 + 0];
    float a = d_gacc[g * 6 + 1];
    float b = d_gacc[g * 6 + 2];
    float c = d_gacc[g * 6 + 3];
    float d = d_gacc[g * 6 + 4];
    float e = d_gacc[g * 6 + 5];
    float diag = s * INV_SQ3;
    out[g * 9 + 0] = diag - c * INV_SQ6 + e * INV_SQ2;
    out[g * 9 + 1] = a * INV_SQ2;
    out[g * 9 + 2] = d * INV_SQ2;
    out[g * 9 + 3] = a * INV_SQ2;
    out[g * 9 + 4] = diag - c * INV_SQ6 - e * INV_SQ2;
    out[g * 9 + 5] = b * INV_SQ2;
    out[g * 9 + 6] = d * INV_SQ2;
    out[g * 9 + 7] = b * INV_SQ2;
    out[g * 9 + 8] = diag + 2.f * c * INV_SQ6;
}

extern "C" void kernel_launch(void* const* d_in, const int* in_sizes, int n_in,
                              void* d_out, int out_size) {
    const float* x     = (const float*)d_in[0];
    const float* xv    = (const float*)d_in[1];
    const float* na    = (const float*)d_in[2];
    const int*   ei    = (const int*)d_in[3];
    const float* Wz    = (const float*)d_in[4];
    const float* Wrad1 = (const float*)d_in[5];
    const float* Wrad2 = (const float*)d_in[6];
    const float* Wp    = (const float*)d_in[7];
    const float* Wr0_1 = (const float*)d_in[8];
    const float* Wr2_1 = (const float*)d_in[9];
    const float* Wm0   = (const float*)d_in[10];
    const float* Wr0_2 = (const float*)d_in[11];
    const float* Wr2_2 = (const float*)d_in[12];
    float* out = (float*)d_out;

    k_init<<<(Gg * NN * CC + 255) / 256, 256>>>(na, Wz);
    k_hist<<<(Gg * NE + 255) / 256, 256>>>(ei);
    k_scan<<<Gg, 1024>>>();
    k_scatter_geom<<<(Gg * NE + 255) / 256, 256>>>(ei, x, xv);
    k_premsg<true><<<(Gg * NE / 32) / 8, 256>>>(Wrad1);
    k_pass<true><<<(Gg * NN * 32) / 256, 256>>>(Wp, Wr0_1, Wr2_1, Wm0);
    k_premsg<false><<<(Gg * NE / 32) / 8, 256>>>(Wrad2);
    k_pass<false><<<(Gg * NN * 32) / 256, 256>>>(Wp, Wr0_2, Wr2_2, Wm0);
    k_finalize<<<1, 32>>>(out);
}

// round 5
// speedup vs baseline: 1.0295x; 1.0295x over previous
#include <cuda_runtime.h>
#include <cuda_bf16.h>

#define Gg 4
#define NN 4096
#define NE 65536
#define NBES 8
#define CC 32
#define NBLK 296
#define NTHR 256
#define GT   (NBLK * NTHR)
#define NWARP (GT / 32)

// ---- scratch (static __device__, no allocation) ----
__device__ int    d_cnt[Gg * NN];        // zero at module load; re-zeroed in tail
__device__ int    d_rowstart[Gg * NN];
__device__ int    d_cursor[Gg * NN];
__device__ int    d_srcA[Gg * NE];
__device__ float4 d_geom[Gg * NE * 4];   // per-edge CSR record: R[8], Y1[3], Y2[5]
__device__ float  d_h0[Gg * NN * CC];
__device__ float  d_h1[Gg * NN * CC];
__device__ float  d_gacc[Gg * 6];        // zero at load; re-zeroed in tail
__device__ int    g_count = 0;
__device__ volatile int g_gen = 0;

#define PI_OVER_RC   0.5235987755982988f
#define SQRT_2_RC    0.5773502691896258f
#define SQ3F         1.7320508075688772f
#define SQRT15       3.872983346207417f
#define CY2_OVER_SQ6 1.1180339887498949f
#define CY2_OVER_SQ2 1.9364916731037085f
#define SQ2F         1.4142135623730951f
#define INV_SQ6      0.4082482904638631f
#define INV_SQ2      0.7071067811865475f
#define INV_SQ3      0.5773502691896258f

__device__ __forceinline__ void grid_sync() {
    __syncthreads();
    if (threadIdx.x == 0) {
        __threadfence();
        int gen = g_gen;
        if (atomicAdd(&g_count, 1) == NBLK - 1) {
            g_count = 0;
            __threadfence();
            g_gen = gen + 1;
        } else {
            while (g_gen == gen) { __nanosleep(64); }
        }
        __threadfence();
    }
    __syncthreads();
}

// fused message-pass + prod3body + readout (+ optional h-update)
__device__ __forceinline__ void pass_phase(
    const float* __restrict__ hin, float* __restrict__ hout,
    const float* __restrict__ Wrad, const float* __restrict__ Wp,
    const float* __restrict__ Wr0, const float* __restrict__ Wr2,
    const float* sWm0, int gwarp, int lane)
{
    float wr[NBES][3];
#pragma unroll
    for (int b = 0; b < NBES; b++) {
        wr[b][0] = Wrad[b * 96 + lane * 3 + 0];
        wr[b][1] = Wrad[b * 96 + lane * 3 + 1];
        wr[b][2] = Wrad[b * 96 + lane * 3 + 2];
    }
    float wp0 = Wp[lane], wp1 = Wp[CC + lane], wp2 = Wp[2 * CC + lane];
    float wp5 = Wp[5 * CC + lane], wp6 = Wp[6 * CC + lane];
    float wr0 = Wr0[lane], wr2v = Wr2[lane];

    for (int node = gwarp; node < Gg * NN; node += NWARP) {
        int g = node >> 12;
        int n = node & (NN - 1);
        const float* hbase = hin + g * NN * CC + lane;
        int start = d_rowstart[g * NN + n];
        int deg = d_cnt[g * NN + n];
        int p = g * NE + start;

        float a0 = 0.f, a1x = 0.f, a1y = 0.f, a1z = 0.f;
        float q0 = 0.f, q1 = 0.f, q2 = 0.f, q3 = 0.f, q4 = 0.f;

#pragma unroll 2
        for (int i = 0; i < deg; i++) {
            const float4* rec = d_geom + (size_t)(p + i) * 4;
            float4 Ra = rec[0];
            float4 Rb = rec[1];
            float4 Ya = rec[2];
            float4 Yb = rec[3];
            int src = d_srcA[p + i];
            float hs = hbase[src * CC];

            float w0 = Ra.x * wr[0][0] + Ra.y * wr[1][0] + Ra.z * wr[2][0] + Ra.w * wr[3][0]
                     + Rb.x * wr[4][0] + Rb.y * wr[5][0] + Rb.z * wr[6][0] + Rb.w * wr[7][0];
            float w1 = Ra.x * wr[0][1] + Ra.y * wr[1][1] + Ra.z * wr[2][1] + Ra.w * wr[3][1]
                     + Rb.x * wr[4][1] + Rb.y * wr[5][1] + Rb.z * wr[6][1] + Rb.w * wr[7][1];
            float w2 = Ra.x * wr[0][2] + Ra.y * wr[1][2] + Ra.z * wr[2][2] + Ra.w * wr[3][2]
                     + Rb.x * wr[4][2] + Rb.y * wr[5][2] + Rb.z * wr[6][2] + Rb.w * wr[7][2];
            float g0 = w0 * hs, g1 = w1 * hs, g2 = w2 * hs;
            a0 += g0;
            a1x += g1 * Ya.x; a1y += g1 * Ya.y; a1z += g1 * Ya.z;
            q0 += g2 * Ya.w;  q1 += g2 * Yb.x;  q2 += g2 * Yb.y;
            q3 += g2 * Yb.z;  q4 += g2 * Yb.w;
        }

        float d11 = a1x * a1x + a1y * a1y + a1z * a1z;
        float d22 = q0 * q0 + q1 * q1 + q2 * q2 + q3 * q3 + q4 * q4;
        float B0 = wp0 * a0 * a0 + wp1 * d11 + wp2 * d22;

        float t5a = SQ2F * a1x * a1y;
        float t5b = SQ2F * a1y * a1z;
        float t5c = (2.f * a1z * a1z - a1x * a1x - a1y * a1y) * INV_SQ6;
        float t5d = SQ2F * a1x * a1z;
        float t5e = (a1x * a1x - a1y * a1y) * INV_SQ2;
        float B2a = wp5 * a0 * q0 + wp6 * t5a;
        float B2b = wp5 * a0 * q1 + wp6 * t5b;
        float B2c = wp5 * a0 * q2 + wp6 * t5c;
        float B2d = wp5 * a0 * q3 + wp6 * t5d;
        float B2e = wp5 * a0 * q4 + wp6 * t5e;

        float sv = B0 * wr0;
        float t0v = B2a * wr2v, t1v = B2b * wr2v, t2v = B2c * wr2v;
        float t3v = B2d * wr2v, t4v = B2e * wr2v;
#pragma unroll
        for (int off = 16; off; off >>= 1) {
            sv  += __shfl_xor_sync(0xffffffffu, sv, off);
            t0v += __shfl_xor_sync(0xffffffffu, t0v, off);
            t1v += __shfl_xor_sync(0xffffffffu, t1v, off);
            t2v += __shfl_xor_sync(0xffffffffu, t2v, off);
            t3v += __shfl_xor_sync(0xffffffffu, t3v, off);
            t4v += __shfl_xor_sync(0xffffffffu, t4v, off);
        }
        if (lane == 0) {
            atomicAdd(&d_gacc[g * 6 + 0], sv);
            atomicAdd(&d_gacc[g * 6 + 1], t0v);
            atomicAdd(&d_gacc[g * 6 + 2], t1v);
            atomicAdd(&d_gacc[g * 6 + 3], t2v);
            atomicAdd(&d_gacc[g * 6 + 4], t3v);
            atomicAdd(&d_gacc[g * 6 + 5], t4v);
        }

        if (hout) {
            float f = 0.f;
#pragma unroll
            for (int k = 0; k < 32; k++) {
                float bk = __shfl_sync(0xffffffffu, B0, k);
                f += bk * sWm0[k * CC + lane];
            }
            f = f / (1.f + __expf(-f));
            hout[(g * NN + n) * CC + lane] = f;
        }
    }
}

__global__ void __launch_bounds__(NTHR, 2)
mega_kernel(const float* __restrict__ x, const float* __restrict__ xv,
            const float* __restrict__ na, const int* __restrict__ ei,
            const float* __restrict__ Wz,
            const float* __restrict__ Wrad1, const float* __restrict__ Wrad2,
            const float* __restrict__ Wp,
            const float* __restrict__ Wr0_1, const float* __restrict__ Wr2_1,
            const float* __restrict__ Wm0,
            const float* __restrict__ Wr0_2, const float* __restrict__ Wr2_2,
            float* __restrict__ out)
{
    __shared__ float sWm0[CC * CC];
    __shared__ int ssc[NTHR];
    int tid = threadIdx.x;
    int bid = blockIdx.x;
    int gtid = bid * NTHR + tid;
    int lane = tid & 31;
    int gwarp = gtid >> 5;

    for (int i = tid; i < CC * CC; i += NTHR) sWm0[i] = Wm0[i];

    // ---- P0: h0 = na @ Wz ; histogram of dst (d_cnt pre-zeroed) ----
    for (int idx = gtid; idx < Gg * NN * CC; idx += GT) {
        int node = idx / CC;
        int c = idx & (CC - 1);
        const float* a = na + node * 3;
        d_h0[idx] = a[0] * Wz[c] + a[1] * Wz[CC + c] + a[2] * Wz[2 * CC + c];
    }
    for (int idx = gtid; idx < Gg * NE; idx += GT) {
        int g = idx >> 16;
        int e = idx & (NE - 1);
        atomicAdd(&d_cnt[g * NN + (int)ei[g * 2 * NE + NE + e]], 1);
    }
    grid_sync();  // B1

    // ---- P1: exclusive scan (block 0 only; per-graph segmented) ----
    if (bid == 0) {
        int base = tid * 64;                  // 256 threads x 64 = 16384
        int s = 0;
        for (int j = 0; j < 64; j++) s += d_cnt[base + j];
        ssc[tid] = s;
        __syncthreads();
        // block exclusive scan (simple shared-memory scan)
        int val = ssc[tid];
        for (int off = 1; off < NTHR; off <<= 1) {
            int xsh = (tid >= off) ? ssc[tid - off] : 0;
            __syncthreads();
            ssc[tid] += xsh;
            __syncthreads();
        }
        int incl = ssc[tid];
        int excl = incl - val;
        // per-graph reset: graph = tid/64 ; subtract prefix at graph start
        int gstart = (tid >> 6) << 6;
        int gbase = (gstart > 0) ? (ssc[gstart] - ((gstart > 0) ? (ssc[gstart] - (ssc[gstart - 1] + 0)) : 0)) : 0;
        // exclusive prefix at graph start = inclusive at gstart - value at gstart
        int pg = (gstart > 0) ? ssc[gstart - 1] : 0;  // inclusive up to gstart-1 == exclusive at gstart
        (void)gbase;
        int run = excl - pg;
        for (int j = 0; j < 64; j++) {
            int idx = base + j;
            d_rowstart[idx] = run;
            d_cursor[idx] = run;
            run += d_cnt[idx];
        }
    }
    grid_sync();  // B2

    // ---- P2: scatter + per-edge geometry ----
    for (int idx = gtid; idx < Gg * NE; idx += GT) {
        int g = idx >> 16;
        int e = idx & (NE - 1);
        int dst = ei[g * 2 * NE + NE + e];
        int src = ei[g * 2 * NE + e];
        int pos = atomicAdd(&d_cursor[g * NN + dst], 1);
        int p = g * NE + pos;
        d_srcA[p] = src;

        float r = x[g * NE + e];
        const float* v = xv + (g * NE + e) * 3;
        float vx = v[0], vy = v[1], vz = v[2];

        float Rr[8];
        {
            float theta = r * PI_OVER_RC;
            float s1, c1;
            __sincosf(theta, &s1, &c1);
            float tc = c1 + c1;
            float inv = (r > 1e-12f) ? (SQRT_2_RC / r) : 0.f;
            float sm1 = 0.f, sc = s1;
#pragma unroll
            for (int b = 0; b < 8; b++) {
                Rr[b] = sc * inv;
                float nx = tc * sc - sm1;
                sm1 = sc; sc = nx;
            }
            if (r <= 1e-12f) {
#pragma unroll
                for (int b = 0; b < 8; b++) Rr[b] = SQRT_2_RC * (b + 1) * PI_OVER_RC;
            }
        }

        float nv = sqrtf(vx * vx + vy * vy + vz * vz);
        float inu = 1.f / (nv + 1e-9f);
        float ux = vx * inu, uy = vy * inu, uz = vz * inu;
        float ux2 = ux * ux, uy2 = uy * uy, uz2 = uz * uz;

        float4* rec = d_geom + (size_t)p * 4;
        rec[0] = make_float4(Rr[0], Rr[1], Rr[2], Rr[3]);
        rec[1] = make_float4(Rr[4], Rr[5], Rr[6], Rr[7]);
        rec[2] = make_float4(SQ3F * ux, SQ3F * uy, SQ3F * uz, SQRT15 * ux * uy);
        rec[3] = make_float4(SQRT15 * uy * uz,
                             CY2_OVER_SQ6 * (2.f * uz2 - ux2 - uy2),
                             SQRT15 * ux * uz,
                             CY2_OVER_SQ2 * (ux2 - uy2));
    }
    grid_sync();  // B3

    // ---- P3: pass 1 (writes h1) ----
    pass_phase(d_h0, d_h1, Wrad1, Wp, Wr0_1, Wr2_1, sWm0, gwarp, lane);
    grid_sync();  // B4

    // ---- P4: pass 2 ----
    pass_phase(d_h1, (float*)0, Wrad2, Wp, Wr0_2, Wr2_2, sWm0, gwarp, lane);
    grid_sync();  // B5

    // ---- P5: finalize + re-zero scratch for next replay ----
    if (bid == 0 && tid < Gg) {
        int g = tid;
        float s = d_gacc[g * 6 + 0];
        float a = d_gacc[g * 6 + 1];
        float b = d_gacc[g * 6 + 2];
        float c = d_gacc[g * 6 + 3];
        float d = d_gacc[g * 6 + 4];
        float e = d_gacc[g * 6 + 5];
        float diag = s * INV_SQ3;
        out[g * 9 + 0] = diag - c * INV_SQ6 + e * INV_SQ2;
        out[g * 9 + 1] = a * INV_SQ2;
        out[g * 9 + 2] = d * INV_SQ2;
        out[g * 9 + 3] = a * INV_SQ2;
        out[g * 9 + 4] = diag - c * INV_SQ6 - e * INV_SQ2;
        out[g * 9 + 5] = b * INV_SQ2;
        out[g * 9 + 6] = d * INV_SQ2;
        out[g * 9 + 7] = b * INV_SQ2;
        out[g * 9 + 8] = diag + 2.f * c * INV_SQ6;
        // re-zero gacc after reading (same thread -> ordered)
        d_gacc[g * 6 + 0] = 0.f; d_gacc[g * 6 + 1] = 0.f; d_gacc[g * 6 + 2] = 0.f;
        d_gacc[g * 6 + 3] = 0.f; d_gacc[g * 6 + 4] = 0.f; d_gacc[g * 6 + 5] = 0.f;
    }
    // re-zero d_cnt for the next replay (all blocks)
    for (int idx = gtid; idx < Gg * NN; idx += GT) d_cnt[idx] = 0;
}

extern "C" void kernel_launch(void* const* d_in, const int* in_sizes, int n_in,
                              void* d_out, int out_size) {
    const float* x     = (const float*)d_in[0];
    const float* xv    = (const float*)d_in[1];
    const float* na    = (const float*)d_in[2];
    const int*   ei    = (const int*)d_in[3];
    const float* Wz    = (const float*)d_in[4];
    const float* Wrad1 = (const float*)d_in[5];
    const float* Wrad2 = (const float*)d_in[6];
    const float* Wp    = (const float*)d_in[7];
    const float* Wr0_1 = (const float*)d_in[8];
    const float* Wr2_1 = (const float*)d_in[9];
    const float* Wm0   = (const float*)d_in[10];
    const float* Wr0_2 = (const float*)d_in[11];
    const float* Wr2_2 = (const float*)d_in[12];
    float* out = (float*)d_out;

    mega_kernel<<<NBLK, NTHR>>>(x, xv, na, ei, Wz, Wrad1, Wrad2, Wp,
                                Wr0_1, Wr2_1, Wm0, Wr0_2, Wr2_2, out);
}